// round 1
// baseline (speedup 1.0000x reference)
#include <cuda_runtime.h>
#include <math.h>

#define BATCH   16
#define NHEADS  32
#define G       8      // kv heads
#define RQ      4      // query heads per kv head
#define D       128
#define BLK     256    // cache block == kv chunk per CTA
#define MAXB    16     // blocks per sequence
#define NEG_INF (-1e30f)
#define QK_SCALE 0.08838834764831845f  // 1/sqrt(128)

// split-KV partial results: [B, G, chunk, rq] scalars + [.., D] accumulators (~4.3MB)
__device__ float g_pm  [BATCH * G * MAXB * RQ];
__device__ float g_pl  [BATCH * G * MAXB * RQ];
__device__ float g_pacc[BATCH * G * MAXB * RQ * D];

__global__ __launch_bounds__(256)
void attn_chunk_kernel(const float* __restrict__ q,
                       const float* __restrict__ knew,
                       const float* __restrict__ vnew,
                       const float* __restrict__ kcache,
                       const float* __restrict__ vcache,
                       const int*   __restrict__ ctx_lens,
                       const int*   __restrict__ btab,
                       const int*   __restrict__ slot_map)
{
    const int c = blockIdx.x;   // chunk (== cache block index within sequence)
    const int g = blockIdx.y;   // kv head
    const int b = blockIdx.z;   // sequence

    const int ctx   = ctx_lens[b];
    const int start = c * BLK;
    if (start >= ctx) return;
    const int npos = min(BLK, ctx - start);

    const int tid  = threadIdx.x;
    const int lane = tid & 31;
    const int warp = tid >> 5;

    const int blkid = btab[b * MAXB + c];
    const float4* kbase = (const float4*)kcache + ((size_t)blkid * BLK * G + g) * (D / 4);
    const float4* vbase = (const float4*)vcache + ((size_t)blkid * BLK * G + g) * (D / 4);
    const int PSTR = G * (D / 4);  // float4 stride between positions (256)

    // fresh-token substitution: position ctx-1 uses knew/vnew instead of cache
    const int lastLocal = (slot_map[b] >= 0) ? (ctx - 1 - start) : -1000000;
    const float4* knp = (const float4*)knew + (size_t)(b * G + g) * (D / 4);
    const float4* vnp = (const float4*)vnew + (size_t)(b * G + g) * (D / 4);

    // q for the 4 heads of this group, pre-scaled; lane holds dims 4*lane..4*lane+3
    const float4* qb = (const float4*)q + (size_t)(b * NHEADS + g * RQ) * (D / 4);
    float4 q0 = qb[lane];
    float4 q1 = qb[32 + lane];
    float4 q2 = qb[64 + lane];
    float4 q3 = qb[96 + lane];
    q0.x *= QK_SCALE; q0.y *= QK_SCALE; q0.z *= QK_SCALE; q0.w *= QK_SCALE;
    q1.x *= QK_SCALE; q1.y *= QK_SCALE; q1.z *= QK_SCALE; q1.w *= QK_SCALE;
    q2.x *= QK_SCALE; q2.y *= QK_SCALE; q2.z *= QK_SCALE; q2.w *= QK_SCALE;
    q3.x *= QK_SCALE; q3.y *= QK_SCALE; q3.z *= QK_SCALE; q3.w *= QK_SCALE;

    float m0 = NEG_INF, m1 = NEG_INF, m2 = NEG_INF, m3 = NEG_INF;
    float l0 = 0.f, l1 = 0.f, l2 = 0.f, l3 = 0.f;
    float4 a0 = make_float4(0.f, 0.f, 0.f, 0.f);
    float4 a1 = a0, a2 = a0, a3 = a0;

    // warp w handles positions w, w+8, w+16, ... ; 1-ahead software pipeline
    int p = warp;
    float4 kcur, vcur;
    if (p < npos) {
        if (p == lastLocal) { kcur = knp[lane]; vcur = vnp[lane]; }
        else {
            kcur = kbase[(size_t)p * PSTR + lane];
            vcur = vbase[(size_t)p * PSTR + lane];
        }
    }
    while (p < npos) {
        const int pn = p + 8;
        float4 kn, vn;
        if (pn < npos) {
            if (pn == lastLocal) { kn = knp[lane]; vn = vnp[lane]; }
            else {
                kn = kbase[(size_t)pn * PSTR + lane];
                vn = vbase[(size_t)pn * PSTR + lane];
            }
        }

        // 4-head dot products on this position
        float s0 = kcur.x * q0.x + kcur.y * q0.y + kcur.z * q0.z + kcur.w * q0.w;
        float s1 = kcur.x * q1.x + kcur.y * q1.y + kcur.z * q1.z + kcur.w * q1.w;
        float s2 = kcur.x * q2.x + kcur.y * q2.y + kcur.z * q2.z + kcur.w * q2.w;
        float s3 = kcur.x * q3.x + kcur.y * q3.y + kcur.z * q3.z + kcur.w * q3.w;
        #pragma unroll
        for (int off = 16; off > 0; off >>= 1) {
            s0 += __shfl_xor_sync(0xffffffffu, s0, off);
            s1 += __shfl_xor_sync(0xffffffffu, s1, off);
            s2 += __shfl_xor_sync(0xffffffffu, s2, off);
            s3 += __shfl_xor_sync(0xffffffffu, s3, off);
        }

        // online softmax update per head
        {
            float n = fmaxf(m0, s0), al = __expf(m0 - n), pr = __expf(s0 - n);
            m0 = n; l0 = l0 * al + pr;
            a0.x = a0.x * al + pr * vcur.x; a0.y = a0.y * al + pr * vcur.y;
            a0.z = a0.z * al + pr * vcur.z; a0.w = a0.w * al + pr * vcur.w;
        }
        {
            float n = fmaxf(m1, s1), al = __expf(m1 - n), pr = __expf(s1 - n);
            m1 = n; l1 = l1 * al + pr;
            a1.x = a1.x * al + pr * vcur.x; a1.y = a1.y * al + pr * vcur.y;
            a1.z = a1.z * al + pr * vcur.z; a1.w = a1.w * al + pr * vcur.w;
        }
        {
            float n = fmaxf(m2, s2), al = __expf(m2 - n), pr = __expf(s2 - n);
            m2 = n; l2 = l2 * al + pr;
            a2.x = a2.x * al + pr * vcur.x; a2.y = a2.y * al + pr * vcur.y;
            a2.z = a2.z * al + pr * vcur.z; a2.w = a2.w * al + pr * vcur.w;
        }
        {
            float n = fmaxf(m3, s3), al = __expf(m3 - n), pr = __expf(s3 - n);
            m3 = n; l3 = l3 * al + pr;
            a3.x = a3.x * al + pr * vcur.x; a3.y = a3.y * al + pr * vcur.y;
            a3.z = a3.z * al + pr * vcur.z; a3.w = a3.w * al + pr * vcur.w;
        }

        kcur = kn; vcur = vn; p = pn;
    }

    // combine the 8 warps' partials in smem
    __shared__ float  s_m[8][RQ];
    __shared__ float  s_l[8][RQ];
    __shared__ float4 s_acc[8][RQ][32];   // [warp][head][lane] -> 16KB

    if (lane == 0) {
        s_m[warp][0] = m0; s_m[warp][1] = m1; s_m[warp][2] = m2; s_m[warp][3] = m3;
        s_l[warp][0] = l0; s_l[warp][1] = l1; s_l[warp][2] = l2; s_l[warp][3] = l3;
    }
    s_acc[warp][0][lane] = a0;
    s_acc[warp][1][lane] = a1;
    s_acc[warp][2][lane] = a2;
    s_acc[warp][3][lane] = a3;
    __syncthreads();

    const float* af = (const float*)s_acc;   // flat [(w*RQ+h)*D + d]
    for (int item = tid; item < RQ * D; item += 256) {
        const int h = item >> 7;      // item / 128
        const int d = item & 127;
        float M = NEG_INF;
        #pragma unroll
        for (int w = 0; w < 8; w++) M = fmaxf(M, s_m[w][h]);
        float L = 0.f, A = 0.f;
        #pragma unroll
        for (int w = 0; w < 8; w++) {
            const float e = __expf(s_m[w][h] - M);
            L += e * s_l[w][h];
            A += e * af[(w * RQ + h) * D + d];
        }
        const size_t pidx = ((size_t)(b * G + g) * MAXB + c) * RQ + h;
        g_pacc[pidx * D + d] = A;
        if (d == 0) { g_pm[pidx] = M; g_pl[pidx] = L; }
    }
}

__global__ __launch_bounds__(128)
void attn_combine_kernel(const int* __restrict__ ctx_lens,
                         float* __restrict__ out)
{
    const int h = blockIdx.x;   // 0..31
    const int b = blockIdx.y;   // 0..15
    const int g  = h >> 2;
    const int hh = h & 3;
    const int ctx = ctx_lens[b];
    const int nc  = (ctx + BLK - 1) / BLK;
    const int d = threadIdx.x;

    const size_t base = ((size_t)(b * G + g) * MAXB) * RQ + hh;
    float M = NEG_INF;
    for (int c = 0; c < nc; c++) M = fmaxf(M, g_pm[base + (size_t)c * RQ]);
    float L = 0.f, A = 0.f;
    for (int c = 0; c < nc; c++) {
        const float e = __expf(g_pm[base + (size_t)c * RQ] - M);
        L += e * g_pl[base + (size_t)c * RQ];
        A += e * g_pacc[(base + (size_t)c * RQ) * D + d];
    }
    out[((size_t)b * NHEADS + h) * D + d] = A / L;
}

extern "C" void kernel_launch(void* const* d_in, const int* in_sizes, int n_in,
                              void* d_out, int out_size)
{
    const float* q    = (const float*)d_in[0];
    const float* k    = (const float*)d_in[1];
    const float* v    = (const float*)d_in[2];
    const float* kc   = (const float*)d_in[3];
    const float* vc   = (const float*)d_in[4];
    const int*   ctx  = (const int*)d_in[5];
    const int*   btab = (const int*)d_in[6];
    const int*   smap = (const int*)d_in[7];
    float* out = (float*)d_out;

    dim3 grid(MAXB, G, BATCH);            // up to 2048 chunk CTAs
    attn_chunk_kernel<<<grid, 256>>>(q, k, v, kc, vc, ctx, btab, smap);
    attn_combine_kernel<<<dim3(NHEADS, BATCH), D>>>(ctx, out);
}

// round 2
// speedup vs baseline: 1.2897x; 1.2897x over previous
#include <cuda_runtime.h>
#include <math.h>
#include <stdint.h>

#define BATCH   16
#define NHEADS  32
#define G       8      // kv heads
#define RQ      4      // query heads per kv head
#define D       128
#define BLK     256    // cache block == kv chunk per CTA
#define MAXB    16     // blocks per sequence
#define TS      64     // positions per tile
#define PSTR4   (G * (D / 4))   // float4 stride between positions = 256
#define NEG_INF (-1e30f)
#define QK_SCALE 0.08838834764831845f  // 1/sqrt(128)

// split-KV partial results: [B, G, chunk, rq]
__device__ float g_pm  [BATCH * G * MAXB * RQ];
__device__ float g_pl  [BATCH * G * MAXB * RQ];
__device__ float g_pacc[BATCH * G * MAXB * RQ * D];

__device__ __forceinline__ void cp16(uint32_t dst, const void* src) {
    asm volatile("cp.async.cg.shared.global [%0], [%1], 16;" :: "r"(dst), "l"(src));
}
__device__ __forceinline__ void cp_commit() {
    asm volatile("cp.async.commit_group;");
}
template <int N>
__device__ __forceinline__ void cp_wait() {
    asm volatile("cp.async.wait_group %0;" :: "n"(N));
}

// smem layout (float4 units):
//   [0,    2048)  K buf 0   (64 rows x 32 chunks, swizzled)
//   [2048, 4096)  K buf 1
//   [4096, 6144)  V buf     (single, loaded 1 phase ahead of use)
//   [6144, 6272)  q         [chunk][head] float4, pre-scaled
//   [6272, 6336)  p tile    [pos] float4 (4 heads' exp weights)
//   [6336, 6344)  reduction scratch (32 floats)
#define RED_WMAX 0
#define RED_WSUM 8
#define RED_MNEW 16
#define RED_AL   20
#define RED_MRUN 24
#define RED_LRUN 28
#define SMEM_F4  6344
#define SMEM_BYTES (SMEM_F4 * 16)

__global__ __launch_bounds__(128)
void attn_chunk_kernel(const float* __restrict__ q,
                       const float* __restrict__ knew,
                       const float* __restrict__ vnew,
                       const float* __restrict__ kcache,
                       const float* __restrict__ vcache,
                       const int*   __restrict__ ctx_lens,
                       const int*   __restrict__ btab,
                       const int*   __restrict__ slot_map)
{
    const int c = blockIdx.x;   // chunk
    const int g = blockIdx.y;   // kv head
    const int b = blockIdx.z;   // sequence

    const int ctx   = ctx_lens[b];
    const int start = c * BLK;
    if (start >= ctx) return;
    const int npos = min(BLK, ctx - start);

    extern __shared__ float4 sm4[];
    float4* kb[2] = { sm4, sm4 + 2048 };
    float4* vb   = sm4 + 4096;
    float4* qsm  = sm4 + 6144;
    float4* pt   = sm4 + 6272;
    float*  red  = (float*)(sm4 + 6336);

    const int tid  = threadIdx.x;
    const int lane = tid & 31;
    const int warp = tid >> 5;

    const int blkid = btab[b * MAXB + c];
    const float4* kbase = (const float4*)kcache + (size_t)blkid * BLK * PSTR4 + g * (D / 4);
    const float4* vbase = (const float4*)vcache + (size_t)blkid * BLK * PSTR4 + g * (D / 4);

    const int lastLocal = (slot_map[b] >= 0) ? (ctx - 1 - start) : -1000000;
    const float4* knp = (const float4*)knew + (size_t)(b * G + g) * (D / 4);
    const float4* vnp = (const float4*)vnew + (size_t)(b * G + g) * (D / 4);

    // q into smem, pre-scaled, layout [chunk][head]
    {
        const float4* qb = (const float4*)q + (size_t)(b * NHEADS + g * RQ) * (D / 4);
        int cc = tid >> 2, h = tid & 3;
        float4 t4 = qb[h * 32 + cc];
        t4.x *= QK_SCALE; t4.y *= QK_SCALE; t4.z *= QK_SCALE; t4.w *= QK_SCALE;
        qsm[cc * 4 + h] = t4;
    }
    if (tid < 4) { red[RED_MRUN + tid] = NEG_INF; red[RED_LRUN + tid] = 0.f; }

    const uint32_t kb_addr[2] = { (uint32_t)__cvta_generic_to_shared(kb[0]),
                                  (uint32_t)__cvta_generic_to_shared(kb[1]) };
    const uint32_t vb_addr = (uint32_t)__cvta_generic_to_shared(vb);

    const int ntiles = (npos + TS - 1) / TS;

    // prologue: K tile 0 -> buf 0
    {
        int rows = min(TS, npos);
        #pragma unroll
        for (int j = 0; j < 16; ++j) {
            int idx = tid + 128 * j;
            int row = idx >> 5, cc = idx & 31;
            if (row < rows)
                cp16(kb_addr[0] + (uint32_t)((row * 32 + (cc ^ (row & 31))) * 16),
                     kbase + (size_t)row * PSTR4 + cc);
        }
        cp_commit();
    }

    float4 acc0 = make_float4(0.f, 0.f, 0.f, 0.f);
    float4 acc1 = acc0, acc2 = acc0, acc3 = acc0;

    const int spos = tid & 63;          // position within tile (score phase)
    const int h0   = (tid >> 6) * 2;    // head pair

    for (int t = 0; t < ntiles; ++t) {
        const int t0 = t * TS;
        __syncthreads();   // vb / pt free from previous tile

        // issue V(t)
        {
            int rows = min(TS, npos - t0);
            #pragma unroll
            for (int j = 0; j < 16; ++j) {
                int idx = tid + 128 * j;
                int row = idx >> 5, cc = idx & 31;
                if (row < rows)
                    cp16(vb_addr + (uint32_t)((row * 32 + (cc ^ (row & 31))) * 16),
                         vbase + (size_t)(t0 + row) * PSTR4 + cc);
            }
            cp_commit();
        }
        // issue K(t+1)
        if (t + 1 < ntiles) {
            int t1 = t0 + TS;
            int rows = min(TS, npos - t1);
            uint32_t dst = kb_addr[(t + 1) & 1];
            #pragma unroll
            for (int j = 0; j < 16; ++j) {
                int idx = tid + 128 * j;
                int row = idx >> 5, cc = idx & 31;
                if (row < rows)
                    cp16(dst + (uint32_t)((row * 32 + (cc ^ (row & 31))) * 16),
                         kbase + (size_t)(t1 + row) * PSTR4 + cc);
            }
        }
        cp_commit();

        cp_wait<2>();        // K(t) complete
        __syncthreads();

        // fresh-token K substitution
        const int fr = lastLocal - t0;
        if (fr >= 0 && fr < TS) {
            if (tid < 32)
                kb[t & 1][fr * 32 + (tid ^ (fr & 31))] = knp[tid];
            __syncthreads();
        }

        // ---- score phase: thread = (position, head pair) ----
        float s0 = NEG_INF, s1 = NEG_INF;
        const bool pvalid = (t0 + spos) < npos;
        if (pvalid) {
            const float4* krow = kb[t & 1] + spos * 32;
            const int rsw = spos & 31;
            float a0 = 0.f, a1 = 0.f;
            #pragma unroll 8
            for (int cc = 0; cc < 32; ++cc) {
                float4 k4 = krow[cc ^ rsw];
                float4 qa = qsm[cc * 4 + h0];
                float4 qd = qsm[cc * 4 + h0 + 1];
                a0 += k4.x * qa.x + k4.y * qa.y + k4.z * qa.z + k4.w * qa.w;
                a1 += k4.x * qd.x + k4.y * qd.y + k4.z * qd.z + k4.w * qd.w;
            }
            s0 = a0; s1 = a1;
        }

        // warp max (2 heads)
        float w0 = s0, w1 = s1;
        #pragma unroll
        for (int off = 16; off > 0; off >>= 1) {
            w0 = fmaxf(w0, __shfl_xor_sync(0xffffffffu, w0, off));
            w1 = fmaxf(w1, __shfl_xor_sync(0xffffffffu, w1, off));
        }
        if (lane == 0) { red[RED_WMAX + warp * 2] = w0; red[RED_WMAX + warp * 2 + 1] = w1; }
        __syncthreads();

        if (tid < 4) {  // head h = tid: its two warps are 2*(h>>1), 2*(h>>1)+1
            int h = tid;
            float mt = fmaxf(red[RED_WMAX + 4 * (h >> 1) + (h & 1)],
                             red[RED_WMAX + 4 * (h >> 1) + 2 + (h & 1)]);
            float mo = red[RED_MRUN + h];
            float mn = fmaxf(mo, mt);
            red[RED_MNEW + h] = mn;
            red[RED_AL + h]   = __expf(mo - mn);
            red[RED_MRUN + h] = mn;
        }
        __syncthreads();

        float e0 = 0.f, e1 = 0.f;
        if (pvalid) {
            e0 = __expf(s0 - red[RED_MNEW + h0]);
            e1 = __expf(s1 - red[RED_MNEW + h0 + 1]);
        }
        *(float2*)((float*)pt + spos * 4 + h0) = make_float2(e0, e1);

        // warp sum of e
        float u0 = e0, u1 = e1;
        #pragma unroll
        for (int off = 16; off > 0; off >>= 1) {
            u0 += __shfl_xor_sync(0xffffffffu, u0, off);
            u1 += __shfl_xor_sync(0xffffffffu, u1, off);
        }
        if (lane == 0) { red[RED_WSUM + warp * 2] = u0; red[RED_WSUM + warp * 2 + 1] = u1; }

        cp_wait<1>();        // V(t) complete
        __syncthreads();

        if (tid < 4) {
            int h = tid;
            float lt = red[RED_WSUM + 4 * (h >> 1) + (h & 1)] +
                       red[RED_WSUM + 4 * (h >> 1) + 2 + (h & 1)];
            red[RED_LRUN + h] = red[RED_LRUN + h] * red[RED_AL + h] + lt;
        }

        // ---- PV phase: warp w owns positions w, w+4, ... ----
        {
            const float al0 = red[RED_AL + 0], al1 = red[RED_AL + 1];
            const float al2 = red[RED_AL + 2], al3 = red[RED_AL + 3];
            acc0.x *= al0; acc0.y *= al0; acc0.z *= al0; acc0.w *= al0;
            acc1.x *= al1; acc1.y *= al1; acc1.z *= al1; acc1.w *= al1;
            acc2.x *= al2; acc2.y *= al2; acc2.z *= al2; acc2.w *= al2;
            acc3.x *= al3; acc3.y *= al3; acc3.z *= al3; acc3.w *= al3;

            const int pvn = min(TS, npos - t0);
            #pragma unroll 4
            for (int p = warp; p < pvn; p += 4) {
                float4 v4;
                if (t0 + p == lastLocal) v4 = vnp[lane];
                else                     v4 = vb[p * 32 + (lane ^ (p & 31))];
                float4 p4 = pt[p];  // broadcast
                acc0.x += p4.x * v4.x; acc0.y += p4.x * v4.y; acc0.z += p4.x * v4.z; acc0.w += p4.x * v4.w;
                acc1.x += p4.y * v4.x; acc1.y += p4.y * v4.y; acc1.z += p4.y * v4.z; acc1.w += p4.y * v4.w;
                acc2.x += p4.z * v4.x; acc2.y += p4.z * v4.y; acc2.z += p4.z * v4.z; acc2.w += p4.z * v4.w;
                acc3.x += p4.w * v4.x; acc3.y += p4.w * v4.y; acc3.z += p4.w * v4.z; acc3.w += p4.w * v4.w;
            }
        }
    }

    // ---- epilogue: combine 4 warps' partial acc, write split-KV partials ----
    __syncthreads();
    float4* ab = sm4;   // reuse K buf 0: [warp][head][lane] float4 = 512 f4
    ab[(warp * 4 + 0) * 32 + lane] = acc0;
    ab[(warp * 4 + 1) * 32 + lane] = acc1;
    ab[(warp * 4 + 2) * 32 + lane] = acc2;
    ab[(warp * 4 + 3) * 32 + lane] = acc3;
    __syncthreads();

    const float* abf = (const float*)ab;
    const size_t pidx = ((size_t)(b * G + g) * MAXB + c) * RQ;
    #pragma unroll
    for (int e = tid; e < RQ * D; e += 128) {
        int h = e >> 7, d = e & 127;
        float A = abf[(0 * 4 + h) * 128 + d] + abf[(1 * 4 + h) * 128 + d]
                + abf[(2 * 4 + h) * 128 + d] + abf[(3 * 4 + h) * 128 + d];
        g_pacc[(pidx + h) * D + d] = A;
    }
    if (tid < 4) {
        g_pm[pidx + tid] = red[RED_MRUN + tid];
        g_pl[pidx + tid] = red[RED_LRUN + tid];
    }
}

__global__ __launch_bounds__(128)
void attn_combine_kernel(const int* __restrict__ ctx_lens,
                         float* __restrict__ out)
{
    const int h = blockIdx.x;   // 0..31
    const int b = blockIdx.y;   // 0..15
    const int g  = h >> 2;
    const int hh = h & 3;
    const int nc = (ctx_lens[b] + BLK - 1) / BLK;
    const int d  = threadIdx.x;

    const size_t base = ((size_t)(b * G + g) * MAXB) * RQ + hh;

    float mv[MAXB], lv[MAXB], av[MAXB];
    #pragma unroll
    for (int c = 0; c < MAXB; ++c)
        mv[c] = (c < nc) ? g_pm[base + (size_t)c * RQ] : NEG_INF;
    float M = mv[0];
    #pragma unroll
    for (int c = 1; c < MAXB; ++c) M = fmaxf(M, mv[c]);
    #pragma unroll
    for (int c = 0; c < MAXB; ++c) {
        if (c < nc) {
            lv[c] = g_pl[base + (size_t)c * RQ];
            av[c] = g_pacc[(base + (size_t)c * RQ) * D + d];
        } else { lv[c] = 0.f; av[c] = 0.f; }
    }
    float L = 0.f, A = 0.f;
    #pragma unroll
    for (int c = 0; c < MAXB; ++c) {
        const float e = __expf(mv[c] - M);
        L += e * lv[c];
        A += e * av[c];
    }
    out[((size_t)b * NHEADS + h) * D + d] = A / L;
}

extern "C" void kernel_launch(void* const* d_in, const int* in_sizes, int n_in,
                              void* d_out, int out_size)
{
    const float* q    = (const float*)d_in[0];
    const float* k    = (const float*)d_in[1];
    const float* v    = (const float*)d_in[2];
    const float* kc   = (const float*)d_in[3];
    const float* vc   = (const float*)d_in[4];
    const int*   ctx  = (const int*)d_in[5];
    const int*   btab = (const int*)d_in[6];
    const int*   smap = (const int*)d_in[7];
    float* out = (float*)d_out;

    static int smem_set = 0;
    if (!smem_set) {
        cudaFuncSetAttribute(attn_chunk_kernel,
                             cudaFuncAttributeMaxDynamicSharedMemorySize, SMEM_BYTES);
        smem_set = 1;
    }

    dim3 grid(MAXB, G, BATCH);
    attn_chunk_kernel<<<grid, 128, SMEM_BYTES>>>(q, k, v, kc, vc, ctx, btab, smap);
    attn_combine_kernel<<<dim3(NHEADS, BATCH), D>>>(ctx, out);
}